// round 5
// baseline (speedup 1.0000x reference)
#include <cuda_runtime.h>
#include <cuda_bf16.h>

#define NNODE 100000
#define EMAX  1600000
#define CDIM 64

__device__ __align__(16) float g_h[NNODE * CDIM];
__device__ __align__(16) float g_agg[NNODE * CDIM];   // per-layer: segment_sum of hidden
__device__ __align__(16) float g_PA[NNODE * CDIM];
__device__ __align__(16) float g_PB[NNODE * CDIM];
__device__ __align__(16) float g_pd[EMAX * 4];        // pos_diff (edge order), padded float4
__device__ __align__(16) float g_epd[EMAX * 4];       // pos_diff (dst-sorted order)
__device__ int   g_src[EMAX];
__device__ int   g_dst[EMAX];
__device__ int   g_esrc[EMAX];                        // src, dst-sorted order
__device__ int   g_edst[EMAX];                        // dst, dst-sorted order
__device__ int   g_deg[NNODE];
__device__ int   g_cursor[NNODE];
__device__ int   g_bsum[512];
__device__ int   g_boff[512];
__device__ int   g_mode;                              // 1 = int64 indices, 0 = int32

__device__ __forceinline__ float elu_f(float v) {
    return v > 0.f ? v : expm1f(v);
}

// packed fp32x2 helpers (sm_100+)
__device__ __forceinline__ void ffma2(unsigned long long& d, unsigned long long a, unsigned long long b) {
    asm("fma.rn.f32x2 %0, %1, %2, %0;" : "+l"(d) : "l"(a), "l"(b));
}
__device__ __forceinline__ float usum(unsigned long long v) {
    float lo, hi;
    asm("mov.b64 {%0,%1}, %2;" : "=f"(lo), "=f"(hi) : "l"(v));
    return lo + hi;
}
// vector float2 reduction to global (sm_90+)
__device__ __forceinline__ void red_add_v2(float* addr, float x, float y) {
    asm volatile("red.global.add.v2.f32 [%0], {%1, %2};" :: "l"(addr), "f"(x), "f"(y) : "memory");
}

// ------------------------------------------------------------------ probe index dtype
__global__ void probe_kernel(const int* __restrict__ w) {
    if (threadIdx.x == 0 && blockIdx.x == 0) {
        bool all_odd_zero = true;
        for (int i = 1; i < 64; i += 2)
            if (w[i] != 0) { all_odd_zero = false; break; }
        g_mode = all_odd_zero ? 1 : 0;
    }
}

// ------------------------------------------------------------------ zero helpers
__global__ void zero_deg_kernel(int Nn) {
    for (int i = blockIdx.x * blockDim.x + threadIdx.x; i < Nn; i += gridDim.x * blockDim.x)
        g_deg[i] = 0;
}
__global__ void zero_agg_kernel(int n4) {
    float4* p = reinterpret_cast<float4*>(g_agg);
    for (int i = blockIdx.x * blockDim.x + threadIdx.x; i < n4; i += gridDim.x * blockDim.x)
        p[i] = make_float4(0.f, 0.f, 0.f, 0.f);
}

// ------------------------------------------------------------------ convert indices + pos_diff + degree
__global__ void convert_kernel(const int* __restrict__ w, const float* __restrict__ pos, int Ecnt) {
    int mode = g_mode;
    for (int e = blockIdx.x * blockDim.x + threadIdx.x; e < Ecnt; e += gridDim.x * blockDim.x) {
        int s, d;
        if (mode) { s = w[2 * e]; d = w[2 * (Ecnt + e)]; }
        else      { s = w[e];     d = w[Ecnt + e]; }
        s = min(max(s, 0), NNODE - 1);
        d = min(max(d, 0), NNODE - 1);
        g_src[e] = s;
        g_dst[e] = d;
        atomicAdd(&g_deg[d], 1);
        float4 pd;
        pd.x = pos[s * 3 + 0] - pos[d * 3 + 0];
        pd.y = pos[s * 3 + 1] - pos[d * 3 + 1];
        pd.z = pos[s * 3 + 2] - pos[d * 3 + 2];
        pd.w = 0.f;
        reinterpret_cast<float4*>(g_pd)[e] = pd;
    }
}

// ------------------------------------------------------------------ 3-pass exclusive scan of g_deg -> g_cursor
__global__ void scan_sum_kernel(int Nn) {
    __shared__ int sred[256];
    int i = blockIdx.x * 256 + threadIdx.x;
    int v = (i < Nn) ? g_deg[i] : 0;
    sred[threadIdx.x] = v;
    __syncthreads();
    for (int off = 128; off; off >>= 1) {
        if (threadIdx.x < off) sred[threadIdx.x] += sred[threadIdx.x + off];
        __syncthreads();
    }
    if (threadIdx.x == 0) g_bsum[blockIdx.x] = sred[0];
}
__global__ void scan_top_kernel(int nb) {
    __shared__ int s[512];
    int tid = threadIdx.x;
    int v = (tid < nb) ? g_bsum[tid] : 0;
    s[tid] = v;
    __syncthreads();
    for (int off = 1; off < 512; off <<= 1) {
        int t = (tid >= off) ? s[tid - off] : 0;
        __syncthreads();
        s[tid] += t;
        __syncthreads();
    }
    g_boff[tid] = s[tid] - v;   // exclusive
}
__global__ void scan_apply_kernel(int Nn) {
    __shared__ int s[256];
    int i = blockIdx.x * 256 + threadIdx.x;
    int v = (i < Nn) ? g_deg[i] : 0;
    s[threadIdx.x] = v;
    __syncthreads();
    for (int off = 1; off < 256; off <<= 1) {
        int t = (threadIdx.x >= off) ? s[threadIdx.x - off] : 0;
        __syncthreads();
        s[threadIdx.x] += t;
        __syncthreads();
    }
    if (i < Nn) g_cursor[i] = g_boff[blockIdx.x] + s[threadIdx.x] - v;   // exclusive prefix
}

// ------------------------------------------------------------------ bin edges by dst (counting sort scatter)
__global__ void binplace_kernel(int Ecnt) {
    for (int e = blockIdx.x * blockDim.x + threadIdx.x; e < Ecnt; e += gridDim.x * blockDim.x) {
        int d = g_dst[e];
        int p = atomicAdd(&g_cursor[d], 1);
        g_esrc[p] = g_src[e];
        g_edst[p] = d;
        reinterpret_cast<float4*>(g_epd)[p] = reinterpret_cast<const float4*>(g_pd)[e];
    }
}

// ------------------------------------------------------------------ encoder (f32x2)
// h = elu(x·W0 + b0)·W1 + b1
__global__ void encoder_kernel(const float* __restrict__ x,
                               const float* __restrict__ W0, const float* __restrict__ b0,
                               const float* __restrict__ W1, const float* __restrict__ b1,
                               int Nn) {
    extern __shared__ float sm[];
    float* sW1 = sm;            // 4096, kpair-packed
    float* sW0 = sm + 4096;     // 192
    float* sb0 = sm + 4288;     // 64
    float* sb1 = sm + 4352;     // 64
    float* stage = sm + 4416;   // 8 warps * 320

    for (int t = threadIdx.x; t < 4096; t += blockDim.x) {
        int c = t & 3, lane_ = (t >> 2) & 31, kp = t >> 7;
        int k = 2 * kp + (c & 1);
        int col = lane_ + ((c & 2) ? 32 : 0);
        sW1[t] = W1[k * 64 + col];
    }
    for (int t = threadIdx.x; t < 192; t += blockDim.x) sW0[t] = W0[t];
    if (threadIdx.x < 64) { sb0[threadIdx.x] = b0[threadIdx.x]; sb1[threadIdx.x] = b1[threadIdx.x]; }
    __syncthreads();

    int lane = threadIdx.x & 31;
    int wid  = threadIdx.x >> 5;
    float* wbase = stage + wid * 320;
    const ulonglong2* W1v = reinterpret_cast<const ulonglong2*>(sW1);
    const unsigned long long* nU = reinterpret_cast<const unsigned long long*>(wbase);
    float* hF = wbase;

    int wg = blockIdx.x * (blockDim.x >> 5) + wid;
    int ws = gridDim.x * (blockDim.x >> 5);
    for (int base = wg * 4; base < Nn; base += ws * 4) {
        int rL = ((lane >> 1) * 5) * 2 + (lane & 1);
        int rH = ((16 + (lane >> 1)) * 5) * 2 + (lane & 1);
#pragma unroll
        for (int i = 0; i < 4; i++) {
            int n = base + i;
            float h0 = 0.f, h1 = 0.f;
            if (n < Nn) {
                float x0 = __ldg(&x[n * 3 + 0]), x1 = __ldg(&x[n * 3 + 1]), x2 = __ldg(&x[n * 3 + 2]);
                h0 = elu_f(x0 * sW0[lane]      + x1 * sW0[64 + lane]      + x2 * sW0[128 + lane]      + sb0[lane]);
                h1 = elu_f(x0 * sW0[lane + 32] + x1 * sW0[64 + lane + 32] + x2 * sW0[128 + lane + 32] + sb0[lane + 32]);
            }
            hF[rL + 2 * i] = h0;
            hF[rH + 2 * i] = h1;
        }
        __syncwarp();

        unsigned long long a0[4] = {0,0,0,0}, a1[4] = {0,0,0,0};
#pragma unroll 4
        for (int kp = 0; kp < 32; kp++) {
            ulonglong2 w = W1v[kp * 32 + lane];
#pragma unroll
            for (int i = 0; i < 4; i++) {
                unsigned long long v = nU[kp * 5 + i];
                ffma2(a0[i], v, w.x); ffma2(a1[i], v, w.y);
            }
        }
        float b1a = sb1[lane], b1b = sb1[lane + 32];
#pragma unroll
        for (int i = 0; i < 4; i++) {
            int n = base + i;
            if (n < Nn) {
                g_h[n * 64 + lane]      = usum(a0[i]) + b1a;
                g_h[n * 64 + 32 + lane] = usum(a1[i]) + b1b;
            }
        }
        __syncwarp();
    }
}

// ------------------------------------------------------------------ per-layer precompute:
// PA[n] = h[n]·(W0a+W0c),  PB[n] = h[n]·(W0b−W0c) + b0
__global__ void precompute_kernel(const float* __restrict__ E0, const float* __restrict__ eb0, int Nn) {
    extern __shared__ float sm[];
    float* sWA = sm;            // 4096
    float* sWB = sm + 4096;     // 4096
    float* sb0 = sm + 8192;     // 64
    float* stage = sm + 8256;   // 8 warps * 320 floats

    for (int t = threadIdx.x; t < 4096; t += blockDim.x) {
        int c = t & 3, lane_ = (t >> 2) & 31, kp = t >> 7;
        int k = 2 * kp + (c & 1);
        int col = lane_ + ((c & 2) ? 32 : 0);
        float wC = E0[(128 + k) * 64 + col];
        sWA[t] = E0[k * 64 + col] + wC;
        sWB[t] = E0[(64 + k) * 64 + col] - wC;
    }
    if (threadIdx.x < 64) sb0[threadIdx.x] = eb0[threadIdx.x];
    __syncthreads();

    int lane = threadIdx.x & 31;
    int wid  = threadIdx.x >> 5;
    float* wbase = stage + wid * 320;
    float2* nP = reinterpret_cast<float2*>(wbase);
    const ulonglong2* WAv = reinterpret_cast<const ulonglong2*>(sWA);
    const ulonglong2* WBv = reinterpret_cast<const ulonglong2*>(sWB);
    const unsigned long long* nU = reinterpret_cast<const unsigned long long*>(nP);

    int wg = blockIdx.x * (blockDim.x >> 5) + wid;
    int ws = gridDim.x * (blockDim.x >> 5);
    for (int base = wg * 4; base < Nn; base += ws * 4) {
#pragma unroll
        for (int i = 0; i < 4; i++) {
            int n = base + i;
            nP[lane * 5 + i] = (n < Nn) ? reinterpret_cast<const float2*>(g_h + n * 64)[lane]
                                        : make_float2(0.f, 0.f);
        }
        __syncwarp();

        unsigned long long aA0[4] = {0,0,0,0}, aA1[4] = {0,0,0,0};
        unsigned long long aB0[4] = {0,0,0,0}, aB1[4] = {0,0,0,0};
#pragma unroll 4
        for (int kp = 0; kp < 32; kp++) {
            ulonglong2 wa = WAv[kp * 32 + lane];
            ulonglong2 wb = WBv[kp * 32 + lane];
#pragma unroll
            for (int i = 0; i < 4; i++) {
                unsigned long long v = nU[kp * 5 + i];
                ffma2(aA0[i], v, wa.x); ffma2(aA1[i], v, wa.y);
                ffma2(aB0[i], v, wb.x); ffma2(aB1[i], v, wb.y);
            }
        }
        float b0a = sb0[lane], b0b = sb0[lane + 32];
#pragma unroll
        for (int i = 0; i < 4; i++) {
            int n = base + i;
            if (n < Nn) {
                g_PA[n * 64 + lane]      = usum(aA0[i]);
                g_PA[n * 64 + 32 + lane] = usum(aA1[i]);
                g_PB[n * 64 + lane]      = usum(aB0[i]) + b0a;
                g_PB[n * 64 + 32 + lane] = usum(aB1[i]) + b0b;
            }
        }
        __syncwarp();
    }
}

// ------------------------------------------------------------------ edge gather over dst-sorted edges
// hidden = elu(PA[src] + PB[dst] + pd·Wp); accumulate per-dst run in regs; flush red.v2 per run.
__global__ void edge_gather_kernel(const float* __restrict__ Wp, int Ecnt, int chunk) {
    int lane = threadIdx.x & 31;
    int wid  = threadIdx.x >> 5;
    int wg = blockIdx.x * (blockDim.x >> 5) + wid;
    int beg = wg * chunk;
    if (beg >= Ecnt) return;
    int end = min(Ecnt, beg + chunk);

    float2 wp0 = __ldg(&reinterpret_cast<const float2*>(Wp)[lane]);
    float2 wp1 = __ldg(&reinterpret_cast<const float2*>(Wp + 64)[lane]);
    float2 wp2 = __ldg(&reinterpret_cast<const float2*>(Wp + 128)[lane]);

    const float4* epd4 = reinterpret_cast<const float4*>(g_epd);
    const float2* PA2  = reinterpret_cast<const float2*>(g_PA);
    const float2* PB2  = reinterpret_cast<const float2*>(g_PB);

    int cur = -1;
    float ax = 0.f, ay = 0.f, pbx = 0.f, pby = 0.f;

    for (int e0 = beg; e0 < end; e0 += 4) {
        int dv[4], sv[4];
        float4 pdv[4];
        float2 pav[4];
#pragma unroll
        for (int i = 0; i < 4; i++) {
            int e = e0 + i;
            if (e < end) {
                dv[i] = __ldg(&g_edst[e]);
                sv[i] = __ldg(&g_esrc[e]);
                pdv[i] = __ldg(&epd4[e]);
            } else {
                dv[i] = -1; sv[i] = 0;
                pdv[i] = make_float4(0.f, 0.f, 0.f, 0.f);
            }
        }
#pragma unroll
        for (int i = 0; i < 4; i++)
            pav[i] = (dv[i] >= 0) ? __ldg(&PA2[(size_t)sv[i] * 32 + lane]) : make_float2(0.f, 0.f);
#pragma unroll
        for (int i = 0; i < 4; i++) {
            if (dv[i] < 0) continue;
            if (dv[i] != cur) {
                if (cur >= 0) red_add_v2(&g_agg[(size_t)cur * 64 + 2 * lane], ax, ay);
                cur = dv[i];
                ax = 0.f; ay = 0.f;
                float2 pb = __ldg(&PB2[(size_t)cur * 32 + lane]);
                pbx = pb.x; pby = pb.y;
            }
            float hx = elu_f(pav[i].x + pbx + pdv[i].x * wp0.x + pdv[i].y * wp1.x + pdv[i].z * wp2.x);
            float hy = elu_f(pav[i].y + pby + pdv[i].x * wp0.y + pdv[i].y * wp1.y + pdv[i].z * wp2.y);
            ax += hx; ay += hy;
        }
    }
    if (cur >= 0) red_add_v2(&g_agg[(size_t)cur * 64 + 2 * lane], ax, ay);
}

// ------------------------------------------------------------------ fused node update:
// agg = Hsum[n]·eW1 + deg[n]·eb1 ; u = elu([h, agg]·nW0 + nb0)·nW1 + nb1 ; h += u
__global__ void node_fused_kernel(const float* __restrict__ E1, const float* __restrict__ eb1,
                                  const float* __restrict__ W0, const float* __restrict__ b0,
                                  const float* __restrict__ W1, const float* __restrict__ b1,
                                  int Nn) {
    extern __shared__ float sm[];
    float* sE1 = sm;                 // 4096
    float* sW0 = sm + 4096;          // 8192
    float* sW1 = sm + 12288;         // 4096
    float* seb1 = sm + 16384;        // 64
    float* snb0 = sm + 16448;        // 64
    float* snb1 = sm + 16512;        // 64
    float* stage = sm + 16576;       // 8 warps * 640

    for (int t = threadIdx.x; t < 4096; t += blockDim.x) {
        int c = t & 3, lane_ = (t >> 2) & 31, kp = t >> 7;
        int k = 2 * kp + (c & 1);
        int col = lane_ + ((c & 2) ? 32 : 0);
        sE1[t] = E1[k * 64 + col];
        sW1[t] = W1[k * 64 + col];
    }
    for (int t = threadIdx.x; t < 8192; t += blockDim.x) {
        int c = t & 3, lane_ = (t >> 2) & 31, kp = t >> 7;
        int k = 2 * kp + (c & 1);
        int col = lane_ + ((c & 2) ? 32 : 0);
        sW0[t] = W0[k * 64 + col];
    }
    if (threadIdx.x < 64) {
        seb1[threadIdx.x] = eb1[threadIdx.x];
        snb0[threadIdx.x] = b0[threadIdx.x];
        snb1[threadIdx.x] = b1[threadIdx.x];
    }
    __syncthreads();

    int lane = threadIdx.x & 31;
    int wid  = threadIdx.x >> 5;
    float* wbase = stage + wid * 640;
    float2* nP = reinterpret_cast<float2*>(wbase);
    const ulonglong2* E1v = reinterpret_cast<const ulonglong2*>(sE1);
    const ulonglong2* W0v = reinterpret_cast<const ulonglong2*>(sW0);
    const ulonglong2* W1v = reinterpret_cast<const ulonglong2*>(sW1);
    const unsigned long long* nU = reinterpret_cast<const unsigned long long*>(nP);
    float* hF = wbase;

    int wg = blockIdx.x * (blockDim.x >> 5) + wid;
    int ws = gridDim.x * (blockDim.x >> 5);
    for (int base = wg * 4; base < Nn; base += ws * 4) {
        float degf[4];
#pragma unroll
        for (int i = 0; i < 4; i++) {
            int n = base + i;
            if (n < Nn) {
                nP[lane * 5 + i]        = reinterpret_cast<const float2*>(g_h + n * 64)[lane];
                nP[(32 + lane) * 5 + i] = reinterpret_cast<const float2*>(g_agg + n * 64)[lane];
                degf[i] = (float)__ldg(&g_deg[n]);
            } else {
                nP[lane * 5 + i]        = make_float2(0.f, 0.f);
                nP[(32 + lane) * 5 + i] = make_float2(0.f, 0.f);
                degf[i] = 0.f;
            }
        }
        __syncwarp();

        // ---- GEMM1: agg = Hsum·E1 + deg·eb1
        unsigned long long a0[4] = {0,0,0,0}, a1[4] = {0,0,0,0};
#pragma unroll 4
        for (int kp = 0; kp < 32; kp++) {
            ulonglong2 w = E1v[kp * 32 + lane];
#pragma unroll
            for (int i = 0; i < 4; i++) {
                unsigned long long v = nU[(32 + kp) * 5 + i];
                ffma2(a0[i], v, w.x); ffma2(a1[i], v, w.y);
            }
        }
        float e1a = seb1[lane], e1b = seb1[lane + 32];
        float aggL[4], aggH[4];
#pragma unroll
        for (int i = 0; i < 4; i++) {
            aggL[i] = usum(a0[i]) + degf[i] * e1a;
            aggH[i] = usum(a1[i]) + degf[i] * e1b;
        }
        __syncwarp();
        {
            int rL = ((32 + (lane >> 1)) * 5) * 2 + (lane & 1);
            int rH = ((48 + (lane >> 1)) * 5) * 2 + (lane & 1);
#pragma unroll
            for (int i = 0; i < 4; i++) {
                hF[rL + 2 * i] = aggL[i];
                hF[rH + 2 * i] = aggH[i];
            }
        }
        __syncwarp();

        // ---- GEMM2: hidden = elu([h, agg]·W0 + b0)
        unsigned long long c0[4] = {0,0,0,0}, c1[4] = {0,0,0,0};
#pragma unroll 4
        for (int kp = 0; kp < 64; kp++) {
            ulonglong2 w = W0v[kp * 32 + lane];
#pragma unroll
            for (int i = 0; i < 4; i++) {
                unsigned long long v = nU[kp * 5 + i];
                ffma2(c0[i], v, w.x); ffma2(c1[i], v, w.y);
            }
        }
        float b0a = snb0[lane], b0b = snb0[lane + 32];
        float hL[4], hH[4];
#pragma unroll
        for (int i = 0; i < 4; i++) {
            hL[i] = elu_f(usum(c0[i]) + b0a);
            hH[i] = elu_f(usum(c1[i]) + b0b);
        }
        __syncwarp();
        {
            int rL = ((lane >> 1) * 5) * 2 + (lane & 1);
            int rH = ((16 + (lane >> 1)) * 5) * 2 + (lane & 1);
#pragma unroll
            for (int i = 0; i < 4; i++) {
                hF[rL + 2 * i] = hL[i];
                hF[rH + 2 * i] = hH[i];
            }
        }
        __syncwarp();

        // ---- GEMM3: u = hidden·W1 + b1 ; h += u
        unsigned long long d0[4] = {0,0,0,0}, d1[4] = {0,0,0,0};
#pragma unroll 4
        for (int kp = 0; kp < 32; kp++) {
            ulonglong2 w = W1v[kp * 32 + lane];
#pragma unroll
            for (int i = 0; i < 4; i++) {
                unsigned long long v = nU[kp * 5 + i];
                ffma2(d0[i], v, w.x); ffma2(d1[i], v, w.y);
            }
        }
        float b1a = snb1[lane], b1b = snb1[lane + 32];
#pragma unroll
        for (int i = 0; i < 4; i++) {
            int n = base + i;
            if (n < Nn) {
                float old0 = g_h[n * 64 + lane];
                float old1 = g_h[n * 64 + 32 + lane];
                g_h[n * 64 + lane]      = old0 + usum(d0[i]) + b1a;
                g_h[n * 64 + 32 + lane] = old1 + usum(d1[i]) + b1b;
            }
        }
        __syncwarp();
    }
}

// ------------------------------------------------------------------ decoder
__global__ void decoder_kernel(const float* __restrict__ W0, const float* __restrict__ b0,
                               const float* __restrict__ W1, const float* __restrict__ b1,
                               float* __restrict__ out, int Nn) {
    __shared__ float sW0[4096];
    __shared__ float sW1[192];
    __shared__ float sb0[64];
    __shared__ float sb1v[3];
    for (int t = threadIdx.x; t < 4096; t += blockDim.x) {
        int k = t >> 6, idx = t & 63, j = idx >> 1, half = idx & 1;
        sW0[t] = W0[k * 64 + j + (half << 5)];
    }
    for (int t = threadIdx.x; t < 192; t += blockDim.x) sW1[t] = W1[t];
    if (threadIdx.x < 64) sb0[threadIdx.x] = b0[threadIdx.x];
    if (threadIdx.x < 3)  sb1v[threadIdx.x] = b1[threadIdx.x];
    __syncthreads();

    const float2* W0p = reinterpret_cast<const float2*>(sW0);
    int lane = threadIdx.x & 31, wid = threadIdx.x >> 5;
    int wg = blockIdx.x * (blockDim.x >> 5) + wid;
    int ws = gridDim.x * (blockDim.x >> 5);
    for (int n = wg; n < Nn; n += ws) {
        float h0 = g_h[n * 64 + lane], h1 = g_h[n * 64 + 32 + lane];
        float acc0 = sb0[lane], acc1 = sb0[lane + 32];
#pragma unroll
        for (int k = 0; k < 32; k++) { float v = __shfl_sync(~0u, h0, k); float2 w = W0p[k * 32 + lane];        acc0 += v * w.x; acc1 += v * w.y; }
#pragma unroll
        for (int k = 0; k < 32; k++) { float v = __shfl_sync(~0u, h1, k); float2 w = W0p[(32 + k) * 32 + lane]; acc0 += v * w.x; acc1 += v * w.y; }
        float hid0 = elu_f(acc0), hid1 = elu_f(acc1);
        float p0 = hid0 * sW1[lane * 3 + 0] + hid1 * sW1[(lane + 32) * 3 + 0];
        float p1 = hid0 * sW1[lane * 3 + 1] + hid1 * sW1[(lane + 32) * 3 + 1];
        float p2 = hid0 * sW1[lane * 3 + 2] + hid1 * sW1[(lane + 32) * 3 + 2];
#pragma unroll
        for (int off = 16; off; off >>= 1) {
            p0 += __shfl_xor_sync(~0u, p0, off);
            p1 += __shfl_xor_sync(~0u, p1, off);
            p2 += __shfl_xor_sync(~0u, p2, off);
        }
        if (lane == 0) {
            out[n * 3 + 0] = p0 + sb1v[0];
            out[n * 3 + 1] = p1 + sb1v[1];
            out[n * 3 + 2] = p2 + sb1v[2];
        }
    }
}

// ------------------------------------------------------------------ launch
extern "C" void kernel_launch(void* const* d_in, const int* in_sizes, int n_in,
                              void* d_out, int out_size) {
    const float* x      = (const float*)d_in[0];
    const float* pos    = (const float*)d_in[1];
    const int*   ei     = (const int*)d_in[2];   // dtype auto-detected on device
    const float* enc_W0 = (const float*)d_in[3];
    const float* enc_b0 = (const float*)d_in[4];
    const float* enc_W1 = (const float*)d_in[5];
    const float* enc_b1 = (const float*)d_in[6];
    const float* dec_W0 = (const float*)d_in[7];
    const float* dec_b0 = (const float*)d_in[8];
    const float* dec_W1 = (const float*)d_in[9];
    const float* dec_b1 = (const float*)d_in[10];
    const float* eW0    = (const float*)d_in[11];
    const float* eb0    = (const float*)d_in[12];
    const float* eW1    = (const float*)d_in[13];
    const float* eb1    = (const float*)d_in[14];
    const float* nW0    = (const float*)d_in[15];
    const float* nb0    = (const float*)d_in[16];
    const float* nW1    = (const float*)d_in[17];
    const float* nb1    = (const float*)d_in[18];

    int Nn   = in_sizes[0] / 3;
    int Ecnt = in_sizes[2] / 2;
    if (Ecnt > EMAX) Ecnt = EMAX;
    float* out = (float*)d_out;

    const int ENC_SMEM  = (4416 + 8 * 320) * 4;    // 27,904 B
    const int PRE_SMEM  = (8256 + 8 * 320) * 4;    // 43,264 B
    const int NODE_SMEM = (16576 + 8 * 640) * 4;   // 86,784 B
    cudaFuncSetAttribute(precompute_kernel, cudaFuncAttributeMaxDynamicSharedMemorySize, PRE_SMEM);
    cudaFuncSetAttribute(node_fused_kernel, cudaFuncAttributeMaxDynamicSharedMemorySize, NODE_SMEM);

    const int TPB = 256;
    int nscan = (Nn + 255) / 256;                  // 391 for N=100000
    const int EDGE_BLOCKS = 592;
    int nwarps = EDGE_BLOCKS * (TPB / 32);
    int chunk = (Ecnt + nwarps - 1) / nwarps;

    probe_kernel<<<1, 32>>>(ei);
    zero_deg_kernel<<<148, TPB>>>(Nn);
    convert_kernel<<<444, TPB>>>(ei, pos, Ecnt);
    scan_sum_kernel<<<nscan, 256>>>(Nn);
    scan_top_kernel<<<1, 512>>>(nscan);
    scan_apply_kernel<<<nscan, 256>>>(Nn);
    binplace_kernel<<<444, TPB>>>(Ecnt);
    encoder_kernel<<<296, TPB, ENC_SMEM>>>(x, enc_W0, enc_b0, enc_W1, enc_b1, Nn);
    for (int l = 0; l < 2; l++) {
        const float* E0l = eW0 + (size_t)l * 195 * 64;
        precompute_kernel<<<296, TPB, PRE_SMEM>>>(E0l, eb0 + l * 64, Nn);
        zero_agg_kernel<<<444, TPB>>>(Nn * 64 / 4);
        edge_gather_kernel<<<EDGE_BLOCKS, TPB>>>(E0l + 192 * 64, Ecnt, chunk);
        node_fused_kernel<<<296, TPB, NODE_SMEM>>>(eW1 + (size_t)l * 64 * 64, eb1 + l * 64,
                                                   nW0 + (size_t)l * 128 * 64, nb0 + l * 64,
                                                   nW1 + (size_t)l * 64 * 64,  nb1 + l * 64,
                                                   Nn);
    }
    decoder_kernel<<<444, TPB>>>(dec_W0, dec_b0, dec_W1, dec_b1, out, Nn);
}